// round 3
// baseline (speedup 1.0000x reference)
#include <cuda_runtime.h>
#include <math.h>

// Problem dims
#define BATCH 128
#define SEQ   512
#define IDIM  1024
#define HDIM  1024
#define ODIM  1024
#define BH    (BATCH*HDIM)   // 131072
#define M1    (BATCH*SEQ)    // 65536
#define N4    (4*HDIM)       // 4096
#define REC_BLOCKS 256

typedef unsigned long long u64;

// ---------------- packed f32x2 helpers (Blackwell FFMA2) -------------------
__device__ __forceinline__ u64 pk2(float a) {
    u64 r;
    asm("mov.b64 %0, {%1, %1};" : "=l"(r) : "f"(a));
    return r;
}
__device__ __forceinline__ void fma2(u64 &c, u64 a, u64 b) {
    asm("fma.rn.f32x2 %0, %1, %2, %0;" : "+l"(c) : "l"(a), "l"(b));
}
union F2U { u64 u; float f[2]; };

// ---------------- scratch (static device memory; allocation-free) ----------
__device__ float g_pre[(size_t)SEQ*4*BATCH*HDIM]; // [t][g][b][j]   1 GiB
__device__ float g_hbuf[(size_t)SEQ*BATCH*HDIM];  // [t][b][j]      256 MiB
__device__ float g_gbuf[BATCH*N4];                // [b][g*1024+j]  2 MiB
__device__ float g_c[BH];
__device__ float g_n[BH];
__device__ float g_m[BH];

// grid barrier state
__device__ unsigned int g_cnt = 0;
__device__ unsigned int g_gen = 0;

// ---------------- init: zero recurrent state + gate buffer ----------------
__global__ void k_init() {
    int i = blockIdx.x * blockDim.x + threadIdx.x;
    if (i < BH) { g_c[i] = 0.f; g_n[i] = 0.f; g_m[i] = 0.f; }
    if (i < BATCH * N4) g_gbuf[i] = 0.f;
}

// ---------------- phase 1: pre[t][g][b][:] = x[b,t,:] @ Wg[:I] + bg --------
// GEMM: M=65536 (r=b*S+t), N=1024 per gate (grid.z), K=1024.
// BM=128, BN=64, BK=16, TM=8, TN=4, 256 threads. FFMA2 inner loop.
__global__ __launch_bounds__(256) void k_pre(
    const float* __restrict__ x,
    const float* __restrict__ Wf, const float* __restrict__ Wi,
    const float* __restrict__ Wc, const float* __restrict__ Wo,
    const float* __restrict__ bf, const float* __restrict__ bi,
    const float* __restrict__ bc, const float* __restrict__ bo)
{
    __shared__ __align__(16) float As[16][132];   // row stride 528B (16B mult)
    __shared__ __align__(16) float Bs[16][64];

    const int g  = blockIdx.z;
    const float* W    = (g == 0) ? Wf : (g == 1) ? Wi : (g == 2) ? Wc : Wo;
    const float* bias = (g == 0) ? bf : (g == 1) ? bi : (g == 2) ? bc : bo;

    const int n0 = blockIdx.x * 64;
    const int m0 = blockIdx.y * 128;
    const int tid = threadIdx.x;

    const int arow = tid >> 2;          // 0..63
    const int ak4  = (tid & 3) * 4;     // 0,4,8,12
    const int brow = tid >> 4;          // 0..15
    const int bcol = (tid & 15) * 4;    // 0..60

    const int tx = tid & 15;            // col group (TN=4)
    const int ty = tid >> 4;            // row group (TM=8)

    // acc[ip][j]: packed pair of rows (2*ip, 2*ip+1), column j
    F2U acc[4][4];
#pragma unroll
    for (int ip = 0; ip < 4; ip++)
#pragma unroll
        for (int j = 0; j < 4; j++) acc[ip][j].u = 0ull;

    const float* Abase = x + (size_t)m0 * IDIM;

    for (int k0 = 0; k0 < IDIM; k0 += 16) {
        float4 a0 = *(const float4*)(Abase + (size_t)arow        * IDIM + k0 + ak4);
        float4 a1 = *(const float4*)(Abase + (size_t)(arow + 64) * IDIM + k0 + ak4);
        As[ak4 + 0][arow] = a0.x; As[ak4 + 1][arow] = a0.y;
        As[ak4 + 2][arow] = a0.z; As[ak4 + 3][arow] = a0.w;
        As[ak4 + 0][arow + 64] = a1.x; As[ak4 + 1][arow + 64] = a1.y;
        As[ak4 + 2][arow + 64] = a1.z; As[ak4 + 3][arow + 64] = a1.w;

        float4 bld = *(const float4*)(W + (size_t)(k0 + brow) * HDIM + n0 + bcol);
        *(float4*)&Bs[brow][bcol] = bld;

        __syncthreads();
#pragma unroll
        for (int kk = 0; kk < 16; kk++) {
            // A: 8 consecutive rows -> 4 packed pairs (free from LDS.128)
            ulonglong2 aA = *(const ulonglong2*)&As[kk][ty * 8];
            ulonglong2 aB = *(const ulonglong2*)&As[kk][ty * 8 + 4];
            float4 bv = *(const float4*)&Bs[kk][tx * 4];
            u64 b0 = pk2(bv.x), b1 = pk2(bv.y), b2 = pk2(bv.z), b3 = pk2(bv.w);
            fma2(acc[0][0].u, aA.x, b0); fma2(acc[0][1].u, aA.x, b1);
            fma2(acc[0][2].u, aA.x, b2); fma2(acc[0][3].u, aA.x, b3);
            fma2(acc[1][0].u, aA.y, b0); fma2(acc[1][1].u, aA.y, b1);
            fma2(acc[1][2].u, aA.y, b2); fma2(acc[1][3].u, aA.y, b3);
            fma2(acc[2][0].u, aB.x, b0); fma2(acc[2][1].u, aB.x, b1);
            fma2(acc[2][2].u, aB.x, b2); fma2(acc[2][3].u, aB.x, b3);
            fma2(acc[3][0].u, aB.y, b0); fma2(acc[3][1].u, aB.y, b1);
            fma2(acc[3][2].u, aB.y, b2); fma2(acc[3][3].u, aB.y, b3);
        }
        __syncthreads();
    }

    float4 bb = *(const float4*)(bias + n0 + tx * 4);
#pragma unroll
    for (int ip = 0; ip < 4; ip++) {
#pragma unroll
        for (int l = 0; l < 2; l++) {
            int i  = ip * 2 + l;
            int r  = m0 + ty * 8 + i;     // r = b*SEQ + t
            int bbn = r >> 9;             // / 512
            int tt  = r & 511;
            float* out = g_pre + (((size_t)tt * 4 + g) * BATCH + bbn) * HDIM + n0 + tx * 4;
            float4 v;
            v.x = acc[ip][0].f[l] + bb.x; v.y = acc[ip][1].f[l] + bb.y;
            v.z = acc[ip][2].f[l] + bb.z; v.w = acc[ip][3].f[l] + bb.w;
            *(float4*)out = v;
        }
    }
}

// ---------------- grid barrier (256 co-resident CTAs) ----------------------
__device__ __forceinline__ void grid_barrier() {
    __threadfence();              // make this block's stores globally visible
    __syncthreads();
    if (threadIdx.x == 0) {
        unsigned int gen = *(volatile unsigned int*)&g_gen;
        __threadfence();          // order gen read before arrival
        unsigned int old = atomicAdd(&g_cnt, 1u);
        if (old == REC_BLOCKS - 1) {
            g_cnt = 0;
            __threadfence();
            atomicAdd(&g_gen, 1u);
        } else {
            while (*(volatile unsigned int*)&g_gen == gen) { }
        }
        __threadfence();
    }
    __syncthreads();
}

// ---------------- pointwise sLSTM update (one element) ---------------------
__device__ __forceinline__ void pointwise_elem(int t, int i) {
    int b = i >> 10;
    int j = i & 1023;

    const float* pre_t = g_pre + (size_t)t * 4 * BH;
    const float* gb = g_gbuf + (size_t)b * N4 + j;
    float f_log = __ldcg(gb + 0 * 1024) + pre_t[(0 * BATCH + b) * HDIM + j];
    float i_log = __ldcg(gb + 1 * 1024) + pre_t[(1 * BATCH + b) * HDIM + j];
    float c_pre = __ldcg(gb + 2 * 1024) + pre_t[(2 * BATCH + b) * HDIM + j];
    float o_pre = __ldcg(gb + 3 * 1024) + pre_t[(3 * BATCH + b) * HDIM + j];

    float m_prev = g_m[i];
    float c_prev = g_c[i];
    float n_prev = g_n[i];

    float m_new = fmaxf(f_log + m_prev, i_log);
    float i_t   = expf(i_log - m_new);
    float f_t   = expf(f_log + m_prev - m_new);
    float c_hat = tanhf(c_pre);
    float o_t   = 1.f / (1.f + expf(-o_pre));

    float c_new = f_t * c_prev + i_t * c_hat;
    float n_new = f_t * n_prev + i_t;
    float h_new = o_t * (c_new / (n_new + 1e-8f));

    g_c[i] = c_new;
    g_n[i] = n_new;
    g_m[i] = m_new;
    g_hbuf[(size_t)t * BH + i] = h_new;
}

// ---------------- persistent recurrence kernel -----------------------------
// One kernel does all 512 timesteps. Per step: recurrent GEMM
// gbuf = h_{t-1} @ Wh  (M=128, N=4096, K=1024), barrier, pointwise, barrier.
// Grid: 256 blocks x 128 threads (all co-resident). Tiling per block:
// BM=32, BN=64, BK=16, thread tile 4x4 (FFMA2 packed).
__global__ __launch_bounds__(128) void k_recur(
    const float* __restrict__ Wf, const float* __restrict__ Wi,
    const float* __restrict__ Wc, const float* __restrict__ Wo)
{
    __shared__ __align__(16) float As[16][36];    // row stride 144B (16B mult)
    __shared__ __align__(16) float Bs[16][64];

    const int bid = blockIdx.x;                   // 0..255
    const int n0 = (bid & 63) * 64;               // 0..4032
    const int m0 = (bid >> 6) * 32;               // 0,32,64,96
    const int tid = threadIdx.x;

    const int gate = n0 >> 10;
    const int j0   = n0 & 1023;
    const float* W = (gate == 0) ? Wf : (gate == 1) ? Wi : (gate == 2) ? Wc : Wo;
    const float* Wh = W + (size_t)IDIM * HDIM + j0;   // recurrent rows

    const int arow = tid >> 2;          // 0..31
    const int ak4  = (tid & 3) * 4;
    const int brow = tid >> 4;          // 0..7 (+8 second pass)
    const int bcol = (tid & 15) * 4;

    const int tx = tid & 15;            // TN=4 -> 64 cols
    const int ty = tid >> 4;            // TM=4 -> 32 rows

    const int gtid = bid * 128 + tid;   // 0..32767, pointwise base index

    // t = 0: h_prev = 0, gbuf pre-zeroed by k_init
#pragma unroll
    for (int r = 0; r < 4; r++) pointwise_elem(0, gtid + r * 32768);
    grid_barrier();

    for (int t = 1; t < SEQ; t++) {
        const float* A = g_hbuf + (size_t)(t - 1) * BH + (size_t)m0 * HDIM;

        F2U acc[2][4];   // row pairs (2*ip, 2*ip+1) x 4 cols
#pragma unroll
        for (int ip = 0; ip < 2; ip++)
#pragma unroll
            for (int j = 0; j < 4; j++) acc[ip][j].u = 0ull;

        for (int k0 = 0; k0 < HDIM; k0 += 16) {
            float4 a0 = *(const float4*)(A + (size_t)arow * HDIM + k0 + ak4);
            As[ak4 + 0][arow] = a0.x; As[ak4 + 1][arow] = a0.y;
            As[ak4 + 2][arow] = a0.z; As[ak4 + 3][arow] = a0.w;

#pragma unroll
            for (int rr = 0; rr < 2; rr++) {
                int row = brow + rr * 8;
                float4 bld = *(const float4*)(Wh + (size_t)(k0 + row) * HDIM + bcol);
                *(float4*)&Bs[row][bcol] = bld;
            }

            __syncthreads();
#pragma unroll
            for (int kk = 0; kk < 16; kk++) {
                ulonglong2 aP = *(const ulonglong2*)&As[kk][ty * 4]; // pairs (0,1),(2,3)
                float4 bv = *(const float4*)&Bs[kk][tx * 4];
                u64 b0 = pk2(bv.x), b1 = pk2(bv.y), b2 = pk2(bv.z), b3 = pk2(bv.w);
                fma2(acc[0][0].u, aP.x, b0); fma2(acc[0][1].u, aP.x, b1);
                fma2(acc[0][2].u, aP.x, b2); fma2(acc[0][3].u, aP.x, b3);
                fma2(acc[1][0].u, aP.y, b0); fma2(acc[1][1].u, aP.y, b1);
                fma2(acc[1][2].u, aP.y, b2); fma2(acc[1][3].u, aP.y, b3);
            }
            __syncthreads();
        }

#pragma unroll
        for (int ip = 0; ip < 2; ip++) {
#pragma unroll
            for (int l = 0; l < 2; l++) {
                int i = ip * 2 + l;
                int b = m0 + ty * 4 + i;
                float4 v;
                v.x = acc[ip][0].f[l]; v.y = acc[ip][1].f[l];
                v.z = acc[ip][2].f[l]; v.w = acc[ip][3].f[l];
                *(float4*)(g_gbuf + (size_t)b * N4 + n0 + tx * 4) = v;
            }
        }

        grid_barrier();   // gbuf complete

#pragma unroll
        for (int r = 0; r < 4; r++) pointwise_elem(t, gtid + r * 32768);

        grid_barrier();   // h_t complete before next step reads it
    }
}

// ---------------- output GEMM: out[b,t,:] = h_t[b,:] @ Wout + bout ---------
// M=65536 (rA = t*B + b), N=1024, K=1024. Same FFMA2 tiling as k_pre.
__global__ __launch_bounds__(256) void k_out(
    const float* __restrict__ Wout, const float* __restrict__ bout,
    float* __restrict__ out)
{
    __shared__ __align__(16) float As[16][132];
    __shared__ __align__(16) float Bs[16][64];

    const int n0 = blockIdx.x * 64;
    const int m0 = blockIdx.y * 128;
    const int tid = threadIdx.x;

    const int arow = tid >> 2;
    const int ak4  = (tid & 3) * 4;
    const int brow = tid >> 4;
    const int bcol = (tid & 15) * 4;

    const int tx = tid & 15;
    const int ty = tid >> 4;

    F2U acc[4][4];
#pragma unroll
    for (int ip = 0; ip < 4; ip++)
#pragma unroll
        for (int j = 0; j < 4; j++) acc[ip][j].u = 0ull;

    const float* Abase = g_hbuf + (size_t)m0 * HDIM;

    for (int k0 = 0; k0 < HDIM; k0 += 16) {
        float4 a0 = *(const float4*)(Abase + (size_t)arow        * HDIM + k0 + ak4);
        float4 a1 = *(const float4*)(Abase + (size_t)(arow + 64) * HDIM + k0 + ak4);
        As[ak4 + 0][arow] = a0.x; As[ak4 + 1][arow] = a0.y;
        As[ak4 + 2][arow] = a0.z; As[ak4 + 3][arow] = a0.w;
        As[ak4 + 0][arow + 64] = a1.x; As[ak4 + 1][arow + 64] = a1.y;
        As[ak4 + 2][arow + 64] = a1.z; As[ak4 + 3][arow + 64] = a1.w;

        float4 bld = *(const float4*)(Wout + (size_t)(k0 + brow) * ODIM + n0 + bcol);
        *(float4*)&Bs[brow][bcol] = bld;

        __syncthreads();
#pragma unroll
        for (int kk = 0; kk < 16; kk++) {
            ulonglong2 aA = *(const ulonglong2*)&As[kk][ty * 8];
            ulonglong2 aB = *(const ulonglong2*)&As[kk][ty * 8 + 4];
            float4 bv = *(const float4*)&Bs[kk][tx * 4];
            u64 b0 = pk2(bv.x), b1 = pk2(bv.y), b2 = pk2(bv.z), b3 = pk2(bv.w);
            fma2(acc[0][0].u, aA.x, b0); fma2(acc[0][1].u, aA.x, b1);
            fma2(acc[0][2].u, aA.x, b2); fma2(acc[0][3].u, aA.x, b3);
            fma2(acc[1][0].u, aA.y, b0); fma2(acc[1][1].u, aA.y, b1);
            fma2(acc[1][2].u, aA.y, b2); fma2(acc[1][3].u, aA.y, b3);
            fma2(acc[2][0].u, aB.x, b0); fma2(acc[2][1].u, aB.x, b1);
            fma2(acc[2][2].u, aB.x, b2); fma2(acc[2][3].u, aB.x, b3);
            fma2(acc[3][0].u, aB.y, b0); fma2(acc[3][1].u, aB.y, b1);
            fma2(acc[3][2].u, aB.y, b2); fma2(acc[3][3].u, aB.y, b3);
        }
        __syncthreads();
    }

    float4 bb = *(const float4*)(bout + n0 + tx * 4);
#pragma unroll
    for (int ip = 0; ip < 4; ip++) {
#pragma unroll
        for (int l = 0; l < 2; l++) {
            int i  = ip * 2 + l;
            int rA = m0 + ty * 8 + i;     // rA = t*BATCH + b
            int tt = rA >> 7;
            int bbn = rA & 127;
            float* dst = out + ((size_t)bbn * SEQ + tt) * ODIM + n0 + tx * 4;
            float4 v;
            v.x = acc[ip][0].f[l] + bb.x; v.y = acc[ip][1].f[l] + bb.y;
            v.z = acc[ip][2].f[l] + bb.z; v.w = acc[ip][3].f[l] + bb.w;
            *(float4*)dst = v;
        }
    }
}

// ---------------- tail: final h, c, n, m -----------------------------------
__global__ __launch_bounds__(256) void k_tail(float* __restrict__ out) {
    int i = blockIdx.x * blockDim.x + threadIdx.x;   // 0..4*BH
    int which = i / BH;
    int r = i - which * BH;
    float v;
    if (which == 0)      v = g_hbuf[(size_t)(SEQ - 1) * BH + r];
    else if (which == 1) v = g_c[r];
    else if (which == 2) v = g_n[r];
    else                 v = g_m[r];
    out[(size_t)M1 * ODIM + i] = v;
}

// ---------------- launch ----------------------------------------------------
extern "C" void kernel_launch(void* const* d_in, const int* in_sizes, int n_in,
                              void* d_out, int out_size) {
    const float* x    = (const float*)d_in[0];
    const float* Wf   = (const float*)d_in[1];
    const float* bf   = (const float*)d_in[2];
    const float* Wi   = (const float*)d_in[3];
    const float* bi   = (const float*)d_in[4];
    const float* Wc   = (const float*)d_in[5];
    const float* bc   = (const float*)d_in[6];
    const float* Wo   = (const float*)d_in[7];
    const float* bo   = (const float*)d_in[8];
    const float* Wout = (const float*)d_in[9];
    const float* bout = (const float*)d_in[10];
    float* out = (float*)d_out;

    // zero recurrent state + gate buffer (covers BATCH*N4 = 524288)
    k_init<<<2048, 256>>>();

    // phase 1: all x-dependent gate pre-activations (incl. biases)
    dim3 g1(HDIM / 64, M1 / 128, 4);
    k_pre<<<g1, 256>>>(x, Wf, Wi, Wc, Wo, bf, bi, bc, bo);

    // full recurrence in ONE persistent kernel (fixes graph-upload leak)
    k_recur<<<REC_BLOCKS, 128>>>(Wf, Wi, Wc, Wo);

    // batched output projection
    k_out<<<dim3(ODIM / 64, M1 / 128), 256>>>(Wout, bout, out);

    // final h, c, n, m
    k_tail<<<(4 * BH) / 256, 256>>>(out);
}

// round 4
// speedup vs baseline: 1.0563x; 1.0563x over previous
#include <cuda_runtime.h>
#include <math.h>

// Problem dims
#define BATCH 128
#define SEQ   512
#define IDIM  1024
#define HDIM  1024
#define ODIM  1024
#define BH    (BATCH*HDIM)   // 131072
#define M1    (BATCH*SEQ)    // 65536
#define REC_BLOCKS 128

typedef unsigned long long u64;

// ---------------- packed f32x2 helpers (Blackwell FFMA2) -------------------
__device__ __forceinline__ u64 pk2(float a) {
    u64 r;
    asm("mov.b64 %0, {%1, %1};" : "=l"(r) : "f"(a));
    return r;
}
__device__ __forceinline__ void fma2(u64 &c, u64 a, u64 b) {
    asm("fma.rn.f32x2 %0, %1, %2, %0;" : "+l"(c) : "l"(a), "l"(b));
}
union F2U { u64 u; float f[2]; };

// ---------------- scratch (static device memory; allocation-free) ----------
__device__ float g_pre[(size_t)SEQ*4*BATCH*HDIM]; // [t][g][b][j]   1 GiB
__device__ float g_hbuf[(size_t)SEQ*BATCH*HDIM];  // [t][b][j]      256 MiB
__device__ float g_c[BH];
__device__ float g_n[BH];
__device__ float g_m[BH];

// grid barrier state
__device__ unsigned int g_cnt = 0;
__device__ unsigned int g_gen = 0;

// ============================================================================
// Big-GEMM smem layout (k_pre / k_out): double-buffered, A stored DUPLICATED
// (word 2r, 2r+1 both = A[row r]) so packed u64 A operands need no pk2.
// ============================================================================
struct GSmem {
    float As[2][16][264];   // duplicated rows: 256 data words + 8 pad (stride 1056B, 16B mult)
    float Bs[2][16][136];   // 128 data words + 8 pad (stride 544B, 16B mult)
};
#define GSMEM_BYTES ((int)sizeof(GSmem))   // 51200

// Shared inner macro: 16 kk steps, thread tile 8 rows x 4 col-pairs
#define GEMM_COMPUTE(sm, st)                                                  \
    _Pragma("unroll")                                                         \
    for (int kk = 0; kk < 16; kk++) {                                         \
        ulonglong2 aA = *(const ulonglong2*)&sm->As[st][kk][ty*16];           \
        ulonglong2 aB = *(const ulonglong2*)&sm->As[st][kk][ty*16 + 4];       \
        ulonglong2 aC = *(const ulonglong2*)&sm->As[st][kk][ty*16 + 8];       \
        ulonglong2 aD = *(const ulonglong2*)&sm->As[st][kk][ty*16 + 12];      \
        ulonglong2 b0 = *(const ulonglong2*)&sm->Bs[st][kk][tx*8];            \
        ulonglong2 b1 = *(const ulonglong2*)&sm->Bs[st][kk][tx*8 + 4];        \
        fma2(acc[0][0].u, aA.x, b0.x); fma2(acc[0][1].u, aA.x, b0.y);         \
        fma2(acc[0][2].u, aA.x, b1.x); fma2(acc[0][3].u, aA.x, b1.y);         \
        fma2(acc[1][0].u, aA.y, b0.x); fma2(acc[1][1].u, aA.y, b0.y);         \
        fma2(acc[1][2].u, aA.y, b1.x); fma2(acc[1][3].u, aA.y, b1.y);         \
        fma2(acc[2][0].u, aB.x, b0.x); fma2(acc[2][1].u, aB.x, b0.y);         \
        fma2(acc[2][2].u, aB.x, b1.x); fma2(acc[2][3].u, aB.x, b1.y);         \
        fma2(acc[3][0].u, aB.y, b0.x); fma2(acc[3][1].u, aB.y, b0.y);         \
        fma2(acc[3][2].u, aB.y, b1.x); fma2(acc[3][3].u, aB.y, b1.y);         \
        fma2(acc[4][0].u, aC.x, b0.x); fma2(acc[4][1].u, aC.x, b0.y);         \
        fma2(acc[4][2].u, aC.x, b1.x); fma2(acc[4][3].u, aC.x, b1.y);         \
        fma2(acc[5][0].u, aC.y, b0.x); fma2(acc[5][1].u, aC.y, b0.y);         \
        fma2(acc[5][2].u, aC.y, b1.x); fma2(acc[5][3].u, aC.y, b1.y);         \
        fma2(acc[6][0].u, aD.x, b0.x); fma2(acc[6][1].u, aD.x, b0.y);         \
        fma2(acc[6][2].u, aD.x, b1.x); fma2(acc[6][3].u, aD.x, b1.y);         \
        fma2(acc[7][0].u, aD.y, b0.x); fma2(acc[7][1].u, aD.y, b0.y);         \
        fma2(acc[7][2].u, aD.y, b1.x); fma2(acc[7][3].u, aD.y, b1.y);         \
    }

#define GEMM_STORE_STAGE(sm, st)                                              \
    {                                                                         \
        _Pragma("unroll")                                                     \
        for (int q = 0; q < 4; q++)                                           \
            *(u64*)&sm->As[st][lks + q][2*lrow]     = pk2(((const float*)&ra0)[q]); \
        _Pragma("unroll")                                                     \
        for (int q = 0; q < 4; q++)                                           \
            *(u64*)&sm->As[st][lks + 4 + q][2*lrow] = pk2(((const float*)&ra1)[q]); \
        *(float4*)&sm->Bs[st][brow][bcol]     = rb0;                          \
        *(float4*)&sm->Bs[st][brow][bcol + 4] = rb1;                          \
    }

// ---------------- phase 1: pre[t][g][b][:] = x[b,t,:] @ Wg[:I] + bg --------
// GEMM M=65536 (r=b*S+t), N=1024 per gate (grid.z), K=1024.
// Tile 128x128, BK=16, thread tile 8x8, 256 threads, double-buffered.
__global__ __launch_bounds__(256, 2) void k_pre(
    const float* __restrict__ x,
    const float* __restrict__ Wf, const float* __restrict__ Wi,
    const float* __restrict__ Wc, const float* __restrict__ Wo,
    const float* __restrict__ bf, const float* __restrict__ bi,
    const float* __restrict__ bc, const float* __restrict__ bo)
{
    extern __shared__ char smem_raw[];
    GSmem* sm = (GSmem*)smem_raw;

    const int g  = blockIdx.z;
    const float* W    = (g == 0) ? Wf : (g == 1) ? Wi : (g == 2) ? Wc : Wo;
    const float* bias = (g == 0) ? bf : (g == 1) ? bi : (g == 2) ? bc : bo;

    const int n0 = blockIdx.x * 128;
    const int m0 = blockIdx.y * 128;
    const int tid = threadIdx.x;
    const int tx = tid & 15;            // 8 cols each
    const int ty = tid >> 4;            // 8 rows each

    // loader mapping
    const int lrow = tid >> 1;          // A row 0..127
    const int lks  = (tid & 1) * 8;     // A k-offset 0/8
    const int brow = tid >> 4;          // B row 0..15
    const int bcol = (tid & 15) * 8;    // B col

    const float* Aptr = x + (size_t)(m0 + lrow) * IDIM + lks;
    const float* Bptr = W + (size_t)brow * HDIM + n0 + bcol;

    F2U acc[8][4];
#pragma unroll
    for (int i = 0; i < 8; i++)
#pragma unroll
        for (int p = 0; p < 4; p++) acc[i][p].u = 0ull;

    float4 ra0 = *(const float4*)(Aptr);
    float4 ra1 = *(const float4*)(Aptr + 4);
    float4 rb0 = *(const float4*)(Bptr);
    float4 rb1 = *(const float4*)(Bptr + 4);
    GEMM_STORE_STAGE(sm, 0);

    for (int kb = 0; kb < 64; kb++) {
        __syncthreads();
        const int st = kb & 1;
        if (kb + 1 < 64) {
            const int k0 = (kb + 1) * 16;
            ra0 = *(const float4*)(Aptr + k0);
            ra1 = *(const float4*)(Aptr + k0 + 4);
            rb0 = *(const float4*)(Bptr + (size_t)k0 * HDIM);
            rb1 = *(const float4*)(Bptr + (size_t)k0 * HDIM + 4);
        }
        GEMM_COMPUTE(sm, st);
        if (kb + 1 < 64) { const int ns = (kb + 1) & 1; GEMM_STORE_STAGE(sm, ns); }
    }

    float4 bb0 = *(const float4*)(bias + n0 + tx * 8);
    float4 bb1 = *(const float4*)(bias + n0 + tx * 8 + 4);
#pragma unroll
    for (int i = 0; i < 8; i++) {
        int r  = m0 + ty * 8 + i;     // r = b*SEQ + t
        int bbn = r >> 9;
        int tt  = r & 511;
        float* dst = g_pre + (((size_t)tt * 4 + g) * BATCH + bbn) * HDIM + n0 + tx * 8;
        float4 v0, v1;
        v0.x = acc[i][0].f[0] + bb0.x; v0.y = acc[i][0].f[1] + bb0.y;
        v0.z = acc[i][1].f[0] + bb0.z; v0.w = acc[i][1].f[1] + bb0.w;
        v1.x = acc[i][2].f[0] + bb1.x; v1.y = acc[i][2].f[1] + bb1.y;
        v1.z = acc[i][3].f[0] + bb1.z; v1.w = acc[i][3].f[1] + bb1.w;
        *(float4*)dst = v0;
        *(float4*)(dst + 4) = v1;
    }
}

// ---------------- output GEMM: out[b,t,:] = h_t[b,:] @ Wout + bout ---------
__global__ __launch_bounds__(256, 2) void k_out(
    const float* __restrict__ Wout, const float* __restrict__ bout,
    float* __restrict__ out)
{
    extern __shared__ char smem_raw[];
    GSmem* sm = (GSmem*)smem_raw;

    const int n0 = blockIdx.x * 128;
    const int m0 = blockIdx.y * 128;
    const int tid = threadIdx.x;
    const int tx = tid & 15;
    const int ty = tid >> 4;

    const int lrow = tid >> 1;
    const int lks  = (tid & 1) * 8;
    const int brow = tid >> 4;
    const int bcol = (tid & 15) * 8;

    const float* Aptr = g_hbuf + (size_t)(m0 + lrow) * HDIM + lks;
    const float* Bptr = Wout + (size_t)brow * ODIM + n0 + bcol;

    F2U acc[8][4];
#pragma unroll
    for (int i = 0; i < 8; i++)
#pragma unroll
        for (int p = 0; p < 4; p++) acc[i][p].u = 0ull;

    float4 ra0 = *(const float4*)(Aptr);
    float4 ra1 = *(const float4*)(Aptr + 4);
    float4 rb0 = *(const float4*)(Bptr);
    float4 rb1 = *(const float4*)(Bptr + 4);
    GEMM_STORE_STAGE(sm, 0);

    for (int kb = 0; kb < 64; kb++) {
        __syncthreads();
        const int st = kb & 1;
        if (kb + 1 < 64) {
            const int k0 = (kb + 1) * 16;
            ra0 = *(const float4*)(Aptr + k0);
            ra1 = *(const float4*)(Aptr + k0 + 4);
            rb0 = *(const float4*)(Bptr + (size_t)k0 * ODIM);
            rb1 = *(const float4*)(Bptr + (size_t)k0 * ODIM + 4);
        }
        GEMM_COMPUTE(sm, st);
        if (kb + 1 < 64) { const int ns = (kb + 1) & 1; GEMM_STORE_STAGE(sm, ns); }
    }

    float4 bb0 = *(const float4*)(bout + n0 + tx * 8);
    float4 bb1 = *(const float4*)(bout + n0 + tx * 8 + 4);
#pragma unroll
    for (int i = 0; i < 8; i++) {
        int rA = m0 + ty * 8 + i;     // rA = t*BATCH + b
        int tt = rA >> 7;
        int bbn = rA & 127;
        float* dst = out + ((size_t)bbn * SEQ + tt) * ODIM + n0 + tx * 8;
        float4 v0, v1;
        v0.x = acc[i][0].f[0] + bb0.x; v0.y = acc[i][0].f[1] + bb0.y;
        v0.z = acc[i][1].f[0] + bb0.z; v0.w = acc[i][1].f[1] + bb0.w;
        v1.x = acc[i][2].f[0] + bb1.x; v1.y = acc[i][2].f[1] + bb1.y;
        v1.z = acc[i][3].f[0] + bb1.z; v1.w = acc[i][3].f[1] + bb1.w;
        *(float4*)dst = v0;
        *(float4*)(dst + 4) = v1;
    }
}

// ============================================================================
// Persistent recurrence: 128 blocks (1/SM), 256 threads.
// Block owns j-range [bid*8, bid*8+8) for ALL 4 gates, ALL 128 batch rows.
// Recurrent weights (4 gates x 1024 K x 8 j = 128KB) resident in smem.
// Gate pairs (f,i)/(c,o) packed in FFMA2 accs; pointwise fully local;
// c/n/m state lives in registers across all 512 steps. 1 grid barrier/step.
// ============================================================================
struct RSmem {
    float Bsr[1024 * 8 * 4];    // [k][jl][g]  131072 B
    float As[2][16][260];       // duplicated h rows (stride 1040B, 16B mult)
};
#define RSMEM_BYTES ((int)sizeof(RSmem))   // 164352

__device__ __forceinline__ void grid_barrier() {
    __threadfence();
    __syncthreads();
    if (threadIdx.x == 0) {
        unsigned int gen = *(volatile unsigned int*)&g_gen;
        unsigned int old = atomicAdd(&g_cnt, 1u);
        if (old == REC_BLOCKS - 1) {
            g_cnt = 0;
            __threadfence();
            atomicAdd(&g_gen, 1u);
        } else {
            while (*(volatile unsigned int*)&g_gen == gen) __nanosleep(64);
        }
        __threadfence();
    }
    __syncthreads();
}

__global__ __launch_bounds__(256, 1) void k_recur(
    const float* __restrict__ Wf, const float* __restrict__ Wi,
    const float* __restrict__ Wc, const float* __restrict__ Wo)
{
    extern __shared__ char smem_raw[];
    RSmem* sm = (RSmem*)smem_raw;

    const int tid = threadIdx.x;
    const int bid = blockIdx.x;        // 0..127
    const int j0  = bid * 8;
    const int tx  = tid & 7;           // jl 0..7
    const int ty  = tid >> 3;          // 0..31 -> rows ty*4..ty*4+3
    const int jg  = j0 + tx;

    // ---- one-time: load resident recurrent weights Bsr[k][jl][g] ----
    {
        const float* Wm0 = Wf + (size_t)IDIM * HDIM + j0;
        const float* Wm1 = Wi + (size_t)IDIM * HDIM + j0;
        const float* Wm2 = Wc + (size_t)IDIM * HDIM + j0;
        const float* Wm3 = Wo + (size_t)IDIM * HDIM + j0;
        for (int idx = tid; idx < 1024 * 8; idx += 256) {
            int k  = idx >> 3;
            int jl = idx & 7;
            size_t off = (size_t)k * HDIM + jl;
            float* d = &sm->Bsr[(k * 8 + jl) * 4];
            d[0] = Wm0[off]; d[1] = Wm1[off]; d[2] = Wm2[off]; d[3] = Wm3[off];
        }
    }

    // register-resident state
    float cS[4] = {0.f, 0.f, 0.f, 0.f};
    float nS[4] = {0.f, 0.f, 0.f, 0.f};
    float mS[4] = {0.f, 0.f, 0.f, 0.f};

    const int lrow = tid >> 1;          // h row 0..127
    const int lks  = (tid & 1) * 8;

    __syncthreads();   // Bsr ready (block-local)

    for (int t = 0; t < SEQ; t++) {
        // prefetch pre[t][g][row][jg] (independent of GEMM -> latency hidden)
        float pg[4][4];
        {
            const float* preb = g_pre + (size_t)t * 4 * BH;
#pragma unroll
            for (int g = 0; g < 4; g++)
#pragma unroll
                for (int i = 0; i < 4; i++)
                    pg[g][i] = __ldg(preb + (size_t)g * BH + (ty * 4 + i) * HDIM + jg);
        }

        F2U acc[4][2];
#pragma unroll
        for (int i = 0; i < 4; i++) { acc[i][0].u = 0ull; acc[i][1].u = 0ull; }

        if (t > 0) {
            const float* A = g_hbuf + (size_t)(t - 1) * BH + (size_t)lrow * HDIM + lks;
            float4 ra0 = *(const float4*)(A);
            float4 ra1 = *(const float4*)(A + 4);
#pragma unroll
            for (int q = 0; q < 4; q++)
                *(u64*)&sm->As[0][lks + q][2 * lrow]     = pk2(((const float*)&ra0)[q]);
#pragma unroll
            for (int q = 0; q < 4; q++)
                *(u64*)&sm->As[0][lks + 4 + q][2 * lrow] = pk2(((const float*)&ra1)[q]);

            for (int kb = 0; kb < 64; kb++) {
                __syncthreads();
                const int st = kb & 1;
                if (kb + 1 < 64) {
                    const int k0 = (kb + 1) * 16;
                    ra0 = *(const float4*)(A + k0);
                    ra1 = *(const float4*)(A + k0 + 4);
                }
#pragma unroll
                for (int kk = 0; kk < 16; kk++) {
                    const int k = kb * 16 + kk;
                    ulonglong2 aA = *(const ulonglong2*)&sm->As[st][kk][ty * 8];
                    ulonglong2 aB = *(const ulonglong2*)&sm->As[st][kk][ty * 8 + 4];
                    ulonglong2 bv = *(const ulonglong2*)&sm->Bsr[(k * 8 + tx) * 4];
                    fma2(acc[0][0].u, aA.x, bv.x); fma2(acc[0][1].u, aA.x, bv.y);
                    fma2(acc[1][0].u, aA.y, bv.x); fma2(acc[1][1].u, aA.y, bv.y);
                    fma2(acc[2][0].u, aB.x, bv.x); fma2(acc[2][1].u, aB.x, bv.y);
                    fma2(acc[3][0].u, aB.y, bv.x); fma2(acc[3][1].u, aB.y, bv.y);
                }
                if (kb + 1 < 64) {
                    const int ns = (kb + 1) & 1;
#pragma unroll
                    for (int q = 0; q < 4; q++)
                        *(u64*)&sm->As[ns][lks + q][2 * lrow]     = pk2(((const float*)&ra0)[q]);
#pragma unroll
                    for (int q = 0; q < 4; q++)
                        *(u64*)&sm->As[ns][lks + 4 + q][2 * lrow] = pk2(((const float*)&ra1)[q]);
                }
            }
        }

        // pointwise (all 4 gates local in regs)
#pragma unroll
        for (int i = 0; i < 4; i++) {
            float fl = acc[i][0].f[0] + pg[0][i];
            float il = acc[i][0].f[1] + pg[1][i];
            float cl = acc[i][1].f[0] + pg[2][i];
            float ol = acc[i][1].f[1] + pg[3][i];

            float mn = fmaxf(fl + mS[i], il);
            float it = __expf(il - mn);
            float ft = __expf(fl + mS[i] - mn);
            float ch = tanhf(cl);
            float ot = 1.f / (1.f + __expf(-ol));

            float cn = ft * cS[i] + it * ch;
            float nn = ft * nS[i] + it;
            float hn = ot * (cn / (nn + 1e-8f));

            cS[i] = cn; nS[i] = nn; mS[i] = mn;
            g_hbuf[(size_t)t * BH + (ty * 4 + i) * HDIM + jg] = hn;
        }

        grid_barrier();   // h_t visible before any block reads it at t+1
    }

    // final state
#pragma unroll
    for (int i = 0; i < 4; i++) {
        int idx = (ty * 4 + i) * HDIM + jg;
        g_c[idx] = cS[i];
        g_n[idx] = nS[i];
        g_m[idx] = mS[i];
    }
}

// ---------------- tail: final h, c, n, m -----------------------------------
__global__ __launch_bounds__(256) void k_tail(float* __restrict__ out) {
    int i = blockIdx.x * blockDim.x + threadIdx.x;   // 0..4*BH
    int which = i / BH;
    int r = i - which * BH;
    float v;
    if (which == 0)      v = g_hbuf[(size_t)(SEQ - 1) * BH + r];
    else if (which == 1) v = g_c[r];
    else if (which == 2) v = g_n[r];
    else                 v = g_m[r];
    out[(size_t)M1 * ODIM + i] = v;
}

// ---------------- launch ----------------------------------------------------
extern "C" void kernel_launch(void* const* d_in, const int* in_sizes, int n_in,
                              void* d_out, int out_size) {
    const float* x    = (const float*)d_in[0];
    const float* Wf   = (const float*)d_in[1];
    const float* bf   = (const float*)d_in[2];
    const float* Wi   = (const float*)d_in[3];
    const float* bi   = (const float*)d_in[4];
    const float* Wc   = (const float*)d_in[5];
    const float* bc   = (const float*)d_in[6];
    const float* Wo   = (const float*)d_in[7];
    const float* bo   = (const float*)d_in[8];
    const float* Wout = (const float*)d_in[9];
    const float* bout = (const float*)d_in[10];
    float* out = (float*)d_out;

    static int attr_done = 0;
    if (!attr_done) {
        cudaFuncSetAttribute(k_pre,   cudaFuncAttributeMaxDynamicSharedMemorySize, GSMEM_BYTES);
        cudaFuncSetAttribute(k_out,   cudaFuncAttributeMaxDynamicSharedMemorySize, GSMEM_BYTES);
        cudaFuncSetAttribute(k_recur, cudaFuncAttributeMaxDynamicSharedMemorySize, RSMEM_BYTES);
        attr_done = 1;
    }

    // phase 1: all x-dependent gate pre-activations (incl. biases)
    k_pre<<<dim3(HDIM / 128, M1 / 128, 4), 256, GSMEM_BYTES>>>(
        x, Wf, Wi, Wc, Wo, bf, bi, bc, bo);

    // full recurrence, persistent, 1 block/SM
    k_recur<<<REC_BLOCKS, 256, RSMEM_BYTES>>>(Wf, Wi, Wc, Wo);

    // batched output projection
    k_out<<<dim3(ODIM / 128, M1 / 128), 256, GSMEM_BYTES>>>(Wout, bout, out);

    // final h, c, n, m
    k_tail<<<(4 * BH) / 256, 256>>>(out);
}

// round 7
// speedup vs baseline: 1.2116x; 1.1470x over previous
#include <cuda_runtime.h>
#include <math.h>
#include <stdint.h>

// Problem dims
#define BATCH 128
#define SEQ   512
#define IDIM  1024
#define HDIM  1024
#define ODIM  1024
#define BH    (BATCH*HDIM)   // 131072
#define M1    (BATCH*SEQ)    // 65536
#define REC_BLOCKS 128

typedef unsigned long long u64;

// ---------------- packed f32x2 helpers (recurrence kernel) -----------------
__device__ __forceinline__ u64 pk2(float a) {
    u64 r;
    asm("mov.b64 %0, {%1, %1};" : "=l"(r) : "f"(a));
    return r;
}
__device__ __forceinline__ void fma2(u64 &c, u64 a, u64 b) {
    asm("fma.rn.f32x2 %0, %1, %2, %0;" : "+l"(c) : "l"(a), "l"(b));
}
union F2U { u64 u; float f[2]; };

// ---------------- scratch (static device memory; allocation-free) ----------
__device__ float g_pre[(size_t)SEQ*4*BATCH*HDIM]; // [t][g][b][j]   1 GiB
__device__ float g_hbuf[(size_t)SEQ*BATCH*HDIM];  // [t][b][j]      256 MiB
__device__ float g_c[BH];
__device__ float g_n[BH];
__device__ float g_m[BH];

__device__ unsigned int g_cnt = 0;
__device__ unsigned int g_gen = 0;

// ---------------- tf32 helpers ---------------------------------------------
__device__ __forceinline__ uint32_t f2tf32(float f) {
    uint32_t r;
    asm("cvt.rna.tf32.f32 %0, %1;" : "=r"(r) : "f"(f));
    return r;
}
// split v into tf32 hi + tf32 lo (3xTF32 error compensation)
__device__ __forceinline__ void tf32_split(float v, uint32_t &hi, uint32_t &lo) {
    hi = f2tf32(v);
    float r = v - __uint_as_float(hi);
    lo = f2tf32(r);
}
__device__ __forceinline__ void mma_tf32(float* c, const uint32_t* a,
                                         uint32_t b0, uint32_t b1) {
    asm("mma.sync.aligned.m16n8k8.row.col.f32.tf32.tf32.f32 "
        "{%0,%1,%2,%3}, {%4,%5,%6,%7}, {%8,%9}, {%0,%1,%2,%3};"
        : "+f"(c[0]), "+f"(c[1]), "+f"(c[2]), "+f"(c[3])
        : "r"(a[0]), "r"(a[1]), "r"(a[2]), "r"(a[3]), "r"(b0), "r"(b1));
}

// ============================================================================
// 3xTF32 mma.sync GEMM (MODE 0: x @ Wg[:I] + bg -> g_pre,
//                       MODE 1: hbuf @ Wout + bout -> out)
// Tile 128x128, BK=16, 256 threads = 8 warps (4M x 2N), warp tile 32x64.
// Double-buffered hi/lo smem tiles; acc = Ah*Bh + Ah*Bl + Al*Bh (fp32 acc).
// ============================================================================
struct MSmem {
    uint32_t Ah[2][16][136];
    uint32_t Al[2][16][136];
    uint32_t Bh[2][16][136];
    uint32_t Bl[2][16][136];
};
#define MSMEM_BYTES ((int)sizeof(MSmem))   // 69632

template <int MODE>
__global__ __launch_bounds__(256, 2) void k_mma(
    const float* __restrict__ Ag,
    const float* __restrict__ W0, const float* __restrict__ W1,
    const float* __restrict__ W2, const float* __restrict__ W3,
    const float* __restrict__ b0p, const float* __restrict__ b1p,
    const float* __restrict__ b2p, const float* __restrict__ b3p,
    float* __restrict__ dst)
{
    extern __shared__ char smem_raw[];
    MSmem* sm = (MSmem*)smem_raw;

    const int tid  = threadIdx.x;
    const int wid  = tid >> 5;
    const int lane = tid & 31;
    const int gr   = lane >> 2;      // 0..7
    const int cq   = lane & 3;       // 0..3

    const int z = (MODE == 0) ? blockIdx.z : 0;
    const float* W    = (z == 0) ? W0 : (z == 1) ? W1 : (z == 2) ? W2 : W3;
    const float* bias = (z == 0) ? b0p : (z == 1) ? b1p : (z == 2) ? b2p : b3p;
    const float* A    = (MODE == 0) ? Ag : (const float*)g_hbuf;

    const int n0 = blockIdx.x * 128;
    const int m0 = blockIdx.y * 128;

    const int warp_m = (wid & 3) * 32;
    const int warp_n = (wid >> 2) * 64;

    // A loader: row = tid>>1 (0..127), k-offset (tid&1)*8
    const int arow = tid >> 1;
    const int akof = (tid & 1) * 8;
    const float* aptr = A + (size_t)(m0 + arow) * 1024 + akof;

    // B loader: col = (tid&31)*4 contiguous, rows (tid>>5)*2 + {0,1}
    const int bcol = (tid & 31) * 4;
    const int brow = (tid >> 5) * 2;
    const float* bptr = W + (size_t)brow * 1024 + n0 + bcol;

    float acc[2][8][4];
#pragma unroll
    for (int mt = 0; mt < 2; mt++)
#pragma unroll
        for (int nt = 0; nt < 8; nt++)
#pragma unroll
            for (int q = 0; q < 4; q++) acc[mt][nt][q] = 0.f;

#define LOAD_TILE(kb, st)                                                     \
    {                                                                         \
        float av[8];                                                          \
        *(float4*)&av[0] = *(const float4*)(aptr + (kb) * 16);                \
        *(float4*)&av[4] = *(const float4*)(aptr + (kb) * 16 + 4);            \
        _Pragma("unroll")                                                     \
        for (int q = 0; q < 8; q++) {                                         \
            uint32_t hi, lo;                                                  \
            tf32_split(av[q], hi, lo);                                        \
            sm->Ah[st][akof + q][arow] = hi;                                  \
            sm->Al[st][akof + q][arow] = lo;                                  \
        }                                                                     \
        float4 w0 = *(const float4*)(bptr + (size_t)(kb) * 16 * 1024);        \
        float4 w1 = *(const float4*)(bptr + (size_t)((kb) * 16 + 1) * 1024);  \
        uint4 h0, l0, h1, l1;                                                 \
        tf32_split(w0.x, h0.x, l0.x); tf32_split(w0.y, h0.y, l0.y);           \
        tf32_split(w0.z, h0.z, l0.z); tf32_split(w0.w, h0.w, l0.w);           \
        tf32_split(w1.x, h1.x, l1.x); tf32_split(w1.y, h1.y, l1.y);           \
        tf32_split(w1.z, h1.z, l1.z); tf32_split(w1.w, h1.w, l1.w);           \
        *(uint4*)&sm->Bh[st][brow][bcol]     = h0;                            \
        *(uint4*)&sm->Bl[st][brow][bcol]     = l0;                            \
        *(uint4*)&sm->Bh[st][brow + 1][bcol] = h1;                            \
        *(uint4*)&sm->Bl[st][brow + 1][bcol] = l1;                            \
    }

    LOAD_TILE(0, 0);

    for (int kb = 0; kb < 64; kb++) {
        const int st = kb & 1;
        __syncthreads();
        if (kb < 63) LOAD_TILE(kb + 1, st ^ 1);

#pragma unroll
        for (int kt = 0; kt < 2; kt++) {
            uint32_t ah[2][4], al[2][4];
#pragma unroll
            for (int mt = 0; mt < 2; mt++) {
                const int r = warp_m + mt * 16 + gr;
                ah[mt][0] = sm->Ah[st][kt * 8 + cq][r];
                ah[mt][1] = sm->Ah[st][kt * 8 + cq][r + 8];
                ah[mt][2] = sm->Ah[st][kt * 8 + cq + 4][r];
                ah[mt][3] = sm->Ah[st][kt * 8 + cq + 4][r + 8];
                al[mt][0] = sm->Al[st][kt * 8 + cq][r];
                al[mt][1] = sm->Al[st][kt * 8 + cq][r + 8];
                al[mt][2] = sm->Al[st][kt * 8 + cq + 4][r];
                al[mt][3] = sm->Al[st][kt * 8 + cq + 4][r + 8];
            }
#pragma unroll
            for (int nt = 0; nt < 8; nt++) {
                const int cn = warp_n + nt * 8 + gr;
                uint32_t bh0 = sm->Bh[st][kt * 8 + cq][cn];
                uint32_t bh1 = sm->Bh[st][kt * 8 + cq + 4][cn];
                uint32_t bl0 = sm->Bl[st][kt * 8 + cq][cn];
                uint32_t bl1 = sm->Bl[st][kt * 8 + cq + 4][cn];
                // cross terms first, then main (all fp32 accumulate)
                mma_tf32(acc[0][nt], al[0], bh0, bh1);
                mma_tf32(acc[0][nt], ah[0], bl0, bl1);
                mma_tf32(acc[0][nt], ah[0], bh0, bh1);
                mma_tf32(acc[1][nt], al[1], bh0, bh1);
                mma_tf32(acc[1][nt], ah[1], bl0, bl1);
                mma_tf32(acc[1][nt], ah[1], bh0, bh1);
            }
        }
    }
#undef LOAD_TILE

    // ---- epilogue: bias add (fp32 exact) + scatter -------------------------
#pragma unroll
    for (int mt = 0; mt < 2; mt++) {
#pragma unroll
        for (int nt = 0; nt < 8; nt++) {
            const int col = n0 + warp_n + nt * 8 + 2 * cq;
            float2 bv = *(const float2*)(bias + col);
            const int r0 = m0 + warp_m + mt * 16 + gr;
            const int r1 = r0 + 8;
            float2 o0, o1;
            o0.x = acc[mt][nt][0] + bv.x; o0.y = acc[mt][nt][1] + bv.y;
            o1.x = acc[mt][nt][2] + bv.x; o1.y = acc[mt][nt][3] + bv.y;
            if (MODE == 0) {
                int b0i = r0 >> 9, t0i = r0 & 511;
                int b1i = r1 >> 9, t1i = r1 & 511;
                *(float2*)(g_pre + (((size_t)t0i * 4 + z) * BATCH + b0i) * HDIM + col) = o0;
                *(float2*)(g_pre + (((size_t)t1i * 4 + z) * BATCH + b1i) * HDIM + col) = o1;
            } else {
                int t0i = r0 >> 7, b0i = r0 & 127;
                int t1i = r1 >> 7, b1i = r1 & 127;
                *(float2*)(dst + ((size_t)b0i * SEQ + t0i) * ODIM + col) = o0;
                *(float2*)(dst + ((size_t)b1i * SEQ + t1i) * ODIM + col) = o1;
            }
        }
    }
}

// ============================================================================
// Persistent recurrence (unchanged from R4, passing): 128 blocks, 256 thr,
// resident recurrent weights in smem, register-resident c/n/m state,
// 1 grid barrier per step.
// ============================================================================
struct RSmem {
    float Bsr[1024 * 8 * 4];    // [k][jl][g]  131072 B
    float As[2][16][260];       // duplicated h rows (stride 1040B)
};
#define RSMEM_BYTES ((int)sizeof(RSmem))

__device__ __forceinline__ void grid_barrier() {
    __threadfence();
    __syncthreads();
    if (threadIdx.x == 0) {
        unsigned int gen = *(volatile unsigned int*)&g_gen;
        unsigned int old = atomicAdd(&g_cnt, 1u);
        if (old == REC_BLOCKS - 1) {
            g_cnt = 0;
            __threadfence();
            atomicAdd(&g_gen, 1u);
        } else {
            while (*(volatile unsigned int*)&g_gen == gen) __nanosleep(64);
        }
        __threadfence();
    }
    __syncthreads();
}

__global__ __launch_bounds__(256, 1) void k_recur(
    const float* __restrict__ Wf, const float* __restrict__ Wi,
    const float* __restrict__ Wc, const float* __restrict__ Wo)
{
    extern __shared__ char smem_raw[];
    RSmem* sm = (RSmem*)smem_raw;

    const int tid = threadIdx.x;
    const int bid = blockIdx.x;
    const int j0  = bid * 8;
    const int tx  = tid & 7;
    const int ty  = tid >> 3;
    const int jg  = j0 + tx;

    {
        const float* Wm0 = Wf + (size_t)IDIM * HDIM + j0;
        const float* Wm1 = Wi + (size_t)IDIM * HDIM + j0;
        const float* Wm2 = Wc + (size_t)IDIM * HDIM + j0;
        const float* Wm3 = Wo + (size_t)IDIM * HDIM + j0;
        for (int idx = tid; idx < 1024 * 8; idx += 256) {
            int k  = idx >> 3;
            int jl = idx & 7;
            size_t off = (size_t)k * HDIM + jl;
            float* d = &sm->Bsr[(k * 8 + jl) * 4];
            d[0] = Wm0[off]; d[1] = Wm1[off]; d[2] = Wm2[off]; d[3] = Wm3[off];
        }
    }

    float cS[4] = {0.f, 0.f, 0.f, 0.f};
    float nS[4] = {0.f, 0.f, 0.f, 0.f};
    float mS[4] = {0.f, 0.f, 0.f, 0.f};

    const int lrow = tid >> 1;
    const int lks  = (tid & 1) * 8;

    __syncthreads();

    for (int t = 0; t < SEQ; t++) {
        float pg[4][4];
        {
            const float* preb = g_pre + (size_t)t * 4 * BH;
#pragma unroll
            for (int g = 0; g < 4; g++)
#pragma unroll
                for (int i = 0; i < 4; i++)
                    pg[g][i] = __ldg(preb + (size_t)g * BH + (ty * 4 + i) * HDIM + jg);
        }

        F2U acc[4][2];
#pragma unroll
        for (int i = 0; i < 4; i++) { acc[i][0].u = 0ull; acc[i][1].u = 0ull; }

        if (t > 0) {
            const float* A = g_hbuf + (size_t)(t - 1) * BH + (size_t)lrow * HDIM + lks;
            float4 ra0 = *(const float4*)(A);
            float4 ra1 = *(const float4*)(A + 4);
#pragma unroll
            for (int q = 0; q < 4; q++)
                *(u64*)&sm->As[0][lks + q][2 * lrow]     = pk2(((const float*)&ra0)[q]);
#pragma unroll
            for (int q = 0; q < 4; q++)
                *(u64*)&sm->As[0][lks + 4 + q][2 * lrow] = pk2(((const float*)&ra1)[q]);

            for (int kb = 0; kb < 64; kb++) {
                __syncthreads();
                const int st = kb & 1;
                if (kb + 1 < 64) {
                    const int k0 = (kb + 1) * 16;
                    ra0 = *(const float4*)(A + k0);
                    ra1 = *(const float4*)(A + k0 + 4);
                }
#pragma unroll
                for (int kk = 0; kk < 16; kk++) {
                    const int k = kb * 16 + kk;
                    ulonglong2 aA = *(const ulonglong2*)&sm->As[st][kk][ty * 8];
                    ulonglong2 aB = *(const ulonglong2*)&sm->As[st][kk][ty * 8 + 4];
                    ulonglong2 bv = *(const ulonglong2*)&sm->Bsr[(k * 8 + tx) * 4];
                    fma2(acc[0][0].u, aA.x, bv.x); fma2(acc[0][1].u, aA.x, bv.y);
                    fma2(acc[1][0].u, aA.y, bv.x); fma2(acc[1][1].u, aA.y, bv.y);
                    fma2(acc[2][0].u, aB.x, bv.x); fma2(acc[2][1].u, aB.x, bv.y);
                    fma2(acc[3][0].u, aB.y, bv.x); fma2(acc[3][1].u, aB.y, bv.y);
                }
                if (kb + 1 < 64) {
                    const int ns = (kb + 1) & 1;
#pragma unroll
                    for (int q = 0; q < 4; q++)
                        *(u64*)&sm->As[ns][lks + q][2 * lrow]     = pk2(((const float*)&ra0)[q]);
#pragma unroll
                    for (int q = 0; q < 4; q++)
                        *(u64*)&sm->As[ns][lks + 4 + q][2 * lrow] = pk2(((const float*)&ra1)[q]);
                }
            }
        }

#pragma unroll
        for (int i = 0; i < 4; i++) {
            float fl = acc[i][0].f[0] + pg[0][i];
            float il = acc[i][0].f[1] + pg[1][i];
            float cl = acc[i][1].f[0] + pg[2][i];
            float ol = acc[i][1].f[1] + pg[3][i];

            float mn = fmaxf(fl + mS[i], il);
            float it = __expf(il - mn);
            float ft = __expf(fl + mS[i] - mn);
            float ch = tanhf(cl);
            float ot = 1.f / (1.f + __expf(-ol));

            float cn = ft * cS[i] + it * ch;
            float nn = ft * nS[i] + it;
            float hn = ot * (cn / (nn + 1e-8f));

            cS[i] = cn; nS[i] = nn; mS[i] = mn;
            g_hbuf[(size_t)t * BH + (ty * 4 + i) * HDIM + jg] = hn;
        }

        grid_barrier();
    }

#pragma unroll
    for (int i = 0; i < 4; i++) {
        int idx = (ty * 4 + i) * HDIM + jg;
        g_c[idx] = cS[i];
        g_n[idx] = nS[i];
        g_m[idx] = mS[i];
    }
}

// ---------------- tail: final h, c, n, m -----------------------------------
__global__ __launch_bounds__(256) void k_tail(float* __restrict__ out) {
    int i = blockIdx.x * blockDim.x + threadIdx.x;
    int which = i / BH;
    int r = i - which * BH;
    float v;
    if (which == 0)      v = g_hbuf[(size_t)(SEQ - 1) * BH + r];
    else if (which == 1) v = g_c[r];
    else if (which == 2) v = g_n[r];
    else                 v = g_m[r];
    out[(size_t)M1 * ODIM + i] = v;
}

// ---------------- launch ----------------------------------------------------
extern "C" void kernel_launch(void* const* d_in, const int* in_sizes, int n_in,
                              void* d_out, int out_size) {
    const float* x    = (const float*)d_in[0];
    const float* Wf   = (const float*)d_in[1];
    const float* bf   = (const float*)d_in[2];
    const float* Wi   = (const float*)d_in[3];
    const float* bi   = (const float*)d_in[4];
    const float* Wc   = (const float*)d_in[5];
    const float* bc   = (const float*)d_in[6];
    const float* Wo   = (const float*)d_in[7];
    const float* bo   = (const float*)d_in[8];
    const float* Wout = (const float*)d_in[9];
    const float* bout = (const float*)d_in[10];
    float* out = (float*)d_out;

    static int attr_done = 0;
    if (!attr_done) {
        cudaFuncSetAttribute(k_mma<0>, cudaFuncAttributeMaxDynamicSharedMemorySize, MSMEM_BYTES);
        cudaFuncSetAttribute(k_mma<1>, cudaFuncAttributeMaxDynamicSharedMemorySize, MSMEM_BYTES);
        cudaFuncSetAttribute(k_recur,  cudaFuncAttributeMaxDynamicSharedMemorySize, RSMEM_BYTES);
        attr_done = 1;
    }

    // phase 1 (3xTF32 mma.sync): pre[t][g][b][:] = x @ Wg[:I] + bg
    k_mma<0><<<dim3(8, 512, 4), 256, MSMEM_BYTES>>>(
        x, Wf, Wi, Wc, Wo, bf, bi, bc, bo, nullptr);

    // recurrence (fp32, persistent, 1 block/SM)
    k_recur<<<REC_BLOCKS, 256, RSMEM_BYTES>>>(Wf, Wi, Wc, Wo);

    // output projection (3xTF32 mma.sync): out = hbuf @ Wout + bout
    k_mma<1><<<dim3(8, 512, 1), 256, MSMEM_BYTES>>>(
        nullptr, Wout, Wout, Wout, Wout, bout, bout, bout, bout, out);

    // final h, c, n, m
    k_tail<<<(4 * BH) / 256, 256>>>(out);
}

// round 8
// speedup vs baseline: 1.2704x; 1.0485x over previous
#include <cuda_runtime.h>
#include <math.h>
#include <stdint.h>

// Problem dims
#define BATCH 128
#define SEQ   512
#define IDIM  1024
#define HDIM  1024
#define ODIM  1024
#define BH    (BATCH*HDIM)   // 131072
#define M1    (BATCH*SEQ)    // 65536
#define REC_BLOCKS 128

typedef unsigned long long u64;

// ---------------- scratch (static device memory; allocation-free) ----------
__device__ float g_pre[(size_t)SEQ*4*BATCH*HDIM]; // [t][g][b][j]   1 GiB
__device__ float g_hbuf[(size_t)SEQ*BATCH*HDIM];  // [t][b][j]      256 MiB
__device__ float g_c[BH];
__device__ float g_n[BH];
__device__ float g_m[BH];
// recurrent weights split to tf32 hi/lo, layout [128 blocks][32 n][1024 k]
__device__ uint32_t g_whi[(size_t)4096*1024];     // 16 MiB
__device__ uint32_t g_wlo[(size_t)4096*1024];     // 16 MiB

__device__ unsigned int g_cnt = 0;
__device__ unsigned int g_gen = 0;

// ---------------- tf32 helpers ---------------------------------------------
__device__ __forceinline__ uint32_t f2tf32(float f) {
    uint32_t r;
    asm("cvt.rna.tf32.f32 %0, %1;" : "=r"(r) : "f"(f));
    return r;
}
__device__ __forceinline__ void tf32_split(float v, uint32_t &hi, uint32_t &lo) {
    hi = f2tf32(v);
    float r = v - __uint_as_float(hi);
    lo = f2tf32(r);
}
__device__ __forceinline__ void mma_tf32(float* c, const uint32_t* a,
                                         uint32_t b0, uint32_t b1) {
    asm("mma.sync.aligned.m16n8k8.row.col.f32.tf32.tf32.f32 "
        "{%0,%1,%2,%3}, {%4,%5,%6,%7}, {%8,%9}, {%0,%1,%2,%3};"
        : "+f"(c[0]), "+f"(c[1]), "+f"(c[2]), "+f"(c[3])
        : "r"(a[0]), "r"(a[1]), "r"(a[2]), "r"(a[3]), "r"(b0), "r"(b1));
}

// ============================================================================
// 3xTF32 mma.sync GEMM (MODE 0: x @ Wg[:I] + bg -> g_pre,
//                       MODE 1: hbuf @ Wout + bout -> out)    [R7, passing]
// ============================================================================
struct MSmem {
    uint32_t Ah[2][16][136];
    uint32_t Al[2][16][136];
    uint32_t Bh[2][16][136];
    uint32_t Bl[2][16][136];
};
#define MSMEM_BYTES ((int)sizeof(MSmem))   // 69632

template <int MODE>
__global__ __launch_bounds__(256, 2) void k_mma(
    const float* __restrict__ Ag,
    const float* __restrict__ W0, const float* __restrict__ W1,
    const float* __restrict__ W2, const float* __restrict__ W3,
    const float* __restrict__ b0p, const float* __restrict__ b1p,
    const float* __restrict__ b2p, const float* __restrict__ b3p,
    float* __restrict__ dst)
{
    extern __shared__ char smem_raw[];
    MSmem* sm = (MSmem*)smem_raw;

    const int tid  = threadIdx.x;
    const int wid  = tid >> 5;
    const int lane = tid & 31;
    const int gr   = lane >> 2;
    const int cq   = lane & 3;

    const int z = (MODE == 0) ? blockIdx.z : 0;
    const float* W    = (z == 0) ? W0 : (z == 1) ? W1 : (z == 2) ? W2 : W3;
    const float* bias = (z == 0) ? b0p : (z == 1) ? b1p : (z == 2) ? b2p : b3p;
    const float* A    = (MODE == 0) ? Ag : (const float*)g_hbuf;

    const int n0 = blockIdx.x * 128;
    const int m0 = blockIdx.y * 128;

    const int warp_m = (wid & 3) * 32;
    const int warp_n = (wid >> 2) * 64;

    const int arow = tid >> 1;
    const int akof = (tid & 1) * 8;
    const float* aptr = A + (size_t)(m0 + arow) * 1024 + akof;

    const int bcol = (tid & 31) * 4;
    const int brow = (tid >> 5) * 2;
    const float* bptr = W + (size_t)brow * 1024 + n0 + bcol;

    float acc[2][8][4];
#pragma unroll
    for (int mt = 0; mt < 2; mt++)
#pragma unroll
        for (int nt = 0; nt < 8; nt++)
#pragma unroll
            for (int q = 0; q < 4; q++) acc[mt][nt][q] = 0.f;

#define LOAD_TILE(kb, st)                                                     \
    {                                                                         \
        float av[8];                                                          \
        *(float4*)&av[0] = *(const float4*)(aptr + (kb) * 16);                \
        *(float4*)&av[4] = *(const float4*)(aptr + (kb) * 16 + 4);            \
        _Pragma("unroll")                                                     \
        for (int q = 0; q < 8; q++) {                                         \
            uint32_t hi, lo;                                                  \
            tf32_split(av[q], hi, lo);                                        \
            sm->Ah[st][akof + q][arow] = hi;                                  \
            sm->Al[st][akof + q][arow] = lo;                                  \
        }                                                                     \
        float4 w0 = *(const float4*)(bptr + (size_t)(kb) * 16 * 1024);        \
        float4 w1 = *(const float4*)(bptr + (size_t)((kb) * 16 + 1) * 1024);  \
        uint4 h0, l0, h1, l1;                                                 \
        tf32_split(w0.x, h0.x, l0.x); tf32_split(w0.y, h0.y, l0.y);           \
        tf32_split(w0.z, h0.z, l0.z); tf32_split(w0.w, h0.w, l0.w);           \
        tf32_split(w1.x, h1.x, l1.x); tf32_split(w1.y, h1.y, l1.y);           \
        tf32_split(w1.z, h1.z, l1.z); tf32_split(w1.w, h1.w, l1.w);           \
        *(uint4*)&sm->Bh[st][brow][bcol]     = h0;                            \
        *(uint4*)&sm->Bl[st][brow][bcol]     = l0;                            \
        *(uint4*)&sm->Bh[st][brow + 1][bcol] = h1;                            \
        *(uint4*)&sm->Bl[st][brow + 1][bcol] = l1;                            \
    }

    LOAD_TILE(0, 0);

    for (int kb = 0; kb < 64; kb++) {
        const int st = kb & 1;
        __syncthreads();
        if (kb < 63) LOAD_TILE(kb + 1, st ^ 1);

#pragma unroll
        for (int kt = 0; kt < 2; kt++) {
            uint32_t ah[2][4], al[2][4];
#pragma unroll
            for (int mt = 0; mt < 2; mt++) {
                const int r = warp_m + mt * 16 + gr;
                ah[mt][0] = sm->Ah[st][kt * 8 + cq][r];
                ah[mt][1] = sm->Ah[st][kt * 8 + cq][r + 8];
                ah[mt][2] = sm->Ah[st][kt * 8 + cq + 4][r];
                ah[mt][3] = sm->Ah[st][kt * 8 + cq + 4][r + 8];
                al[mt][0] = sm->Al[st][kt * 8 + cq][r];
                al[mt][1] = sm->Al[st][kt * 8 + cq][r + 8];
                al[mt][2] = sm->Al[st][kt * 8 + cq + 4][r];
                al[mt][3] = sm->Al[st][kt * 8 + cq + 4][r + 8];
            }
#pragma unroll
            for (int nt = 0; nt < 8; nt++) {
                const int cn = warp_n + nt * 8 + gr;
                uint32_t bh0 = sm->Bh[st][kt * 8 + cq][cn];
                uint32_t bh1 = sm->Bh[st][kt * 8 + cq + 4][cn];
                uint32_t bl0 = sm->Bl[st][kt * 8 + cq][cn];
                uint32_t bl1 = sm->Bl[st][kt * 8 + cq + 4][cn];
                mma_tf32(acc[0][nt], al[0], bh0, bh1);
                mma_tf32(acc[0][nt], ah[0], bl0, bl1);
                mma_tf32(acc[0][nt], ah[0], bh0, bh1);
                mma_tf32(acc[1][nt], al[1], bh0, bh1);
                mma_tf32(acc[1][nt], ah[1], bl0, bl1);
                mma_tf32(acc[1][nt], ah[1], bh0, bh1);
            }
        }
    }
#undef LOAD_TILE

#pragma unroll
    for (int mt = 0; mt < 2; mt++) {
#pragma unroll
        for (int nt = 0; nt < 8; nt++) {
            const int col = n0 + warp_n + nt * 8 + 2 * cq;
            float2 bv = *(const float2*)(bias + col);
            const int r0 = m0 + warp_m + mt * 16 + gr;
            const int r1 = r0 + 8;
            float2 o0, o1;
            o0.x = acc[mt][nt][0] + bv.x; o0.y = acc[mt][nt][1] + bv.y;
            o1.x = acc[mt][nt][2] + bv.x; o1.y = acc[mt][nt][3] + bv.y;
            if (MODE == 0) {
                int b0i = r0 >> 9, t0i = r0 & 511;
                int b1i = r1 >> 9, t1i = r1 & 511;
                *(float2*)(g_pre + (((size_t)t0i * 4 + z) * BATCH + b0i) * HDIM + col) = o0;
                *(float2*)(g_pre + (((size_t)t1i * 4 + z) * BATCH + b1i) * HDIM + col) = o1;
            } else {
                int t0i = r0 >> 7, b0i = r0 & 127;
                int t1i = r1 >> 7, b1i = r1 & 127;
                *(float2*)(dst + ((size_t)b0i * SEQ + t0i) * ODIM + col) = o0;
                *(float2*)(dst + ((size_t)b1i * SEQ + t1i) * ODIM + col) = o1;
            }
        }
    }
}

// ============================================================================
// prep: split recurrent weights into tf32 hi/lo, layout [blk][32 n][1024 k]
// n-local = g*8 + jl ; global j = blk*8 + jl
// ============================================================================
__global__ __launch_bounds__(256) void k_split(
    const float* __restrict__ Wf, const float* __restrict__ Wi,
    const float* __restrict__ Wc, const float* __restrict__ Wo)
{
    const int np = blockIdx.x;                  // 0..4095
    const int k  = blockIdx.y * 256 + threadIdx.x;
    const int blk = np >> 5, loc = np & 31;
    const int g = loc >> 3, jl = loc & 7;
    const int j = blk * 8 + jl;
    const float* W = (g == 0) ? Wf : (g == 1) ? Wi : (g == 2) ? Wc : Wo;
    float v = W[(size_t)(IDIM + k) * HDIM + j];
    uint32_t hi, lo;
    tf32_split(v, hi, lo);
    g_whi[(size_t)np * 1024 + k] = hi;
    g_wlo[(size_t)np * 1024 + k] = lo;
}

// ============================================================================
// Persistent 3xTF32 recurrence: 128 CTAs (1/SM), 256 threads (8 warps).
// CTA owns 8 j-cols x 4 gates (N=32), all 128 batch rows. Per step:
// GEMM M=128,N=32,K=1024 (BK=32, double-buffered hi/lo smem), acc -> Gbuf,
// CTA-local pointwise with register-resident c/n/m, 1 grid barrier/step.
// ============================================================================
struct R2Smem {
    uint32_t Ah[2][128][36];   // [stage][m][k]  18432 B/stage
    uint32_t Al[2][128][36];
    uint32_t Bh[2][32][36];    // [stage][n][k]  4608 B/stage
    uint32_t Bl[2][32][36];
    float    Gbuf[128][36];    // gate sums [b][n]
};
#define R2SMEM_BYTES ((int)sizeof(R2Smem))   // ~110 KB

__device__ __forceinline__ void grid_barrier() {
    __threadfence();
    __syncthreads();
    if (threadIdx.x == 0) {
        unsigned int gen = *(volatile unsigned int*)&g_gen;
        unsigned int old = atomicAdd(&g_cnt, 1u);
        if (old == REC_BLOCKS - 1) {
            g_cnt = 0;
            __threadfence();
            atomicAdd(&g_gen, 1u);
        } else {
            while (*(volatile unsigned int*)&g_gen == gen) __nanosleep(64);
        }
        __threadfence();
    }
    __syncthreads();
}

__global__ __launch_bounds__(256, 1) void k_recur2() {
    extern __shared__ char smem_raw[];
    R2Smem* sm = (R2Smem*)smem_raw;

    const int tid  = threadIdx.x;
    const int wid  = tid >> 5;
    const int lane = tid & 31;
    const int gr   = lane >> 2;
    const int cq   = lane & 3;
    const int bid  = blockIdx.x;       // 0..127
    const int j0   = bid * 8;

    const int warp_m = (wid & 3) * 32;
    const int warp_n = (wid >> 2) * 16;

    // A loader: row = tid>>1, k-offset (tid&1)*16 (16 floats per thread/tile)
    const int arow = tid >> 1;
    const int akof = (tid & 1) * 16;
    // B loader: n = tid>>3, k-offset (tid&7)*4
    const int bn   = tid >> 3;
    const int bkof = (tid & 7) * 4;
    const uint32_t* whi = g_whi + (size_t)bid * 32 * 1024;
    const uint32_t* wlo = g_wlo + (size_t)bid * 32 * 1024;

    // pointwise: thread owns (b = tid>>1, jl = (tid&1)*4 + e), e = 0..3
    const int pb = tid >> 1;
    const int pj = (tid & 1) * 4;

    float cS[4] = {0.f, 0.f, 0.f, 0.f};
    float nS[4] = {0.f, 0.f, 0.f, 0.f};
    float mS[4] = {0.f, 0.f, 0.f, 0.f};

#define RLOADA(kb, st)                                                        \
    {                                                                         \
        const float* ap = Abase + (size_t)arow * 1024 + (kb) * 32 + akof;     \
        _Pragma("unroll")                                                     \
        for (int q = 0; q < 4; q++) {                                         \
            float4 v = *(const float4*)(ap + q * 4);                          \
            uint4 h, l;                                                       \
            tf32_split(v.x, h.x, l.x); tf32_split(v.y, h.y, l.y);             \
            tf32_split(v.z, h.z, l.z); tf32_split(v.w, h.w, l.w);             \
            *(uint4*)&sm->Ah[st][arow][akof + q * 4] = h;                     \
            *(uint4*)&sm->Al[st][arow][akof + q * 4] = l;                     \
        }                                                                     \
    }
#define RLOADB(kb, st)                                                        \
    {                                                                         \
        uint4 h = *(const uint4*)(whi + (size_t)bn * 1024 + (kb) * 32 + bkof);\
        uint4 l = *(const uint4*)(wlo + (size_t)bn * 1024 + (kb) * 32 + bkof);\
        *(uint4*)&sm->Bh[st][bn][bkof] = h;                                   \
        *(uint4*)&sm->Bl[st][bn][bkof] = l;                                   \
    }

    for (int t = 0; t < SEQ; t++) {
        float acc[2][2][4];
#pragma unroll
        for (int mt = 0; mt < 2; mt++)
#pragma unroll
            for (int nt = 0; nt < 2; nt++)
#pragma unroll
                for (int q = 0; q < 4; q++) acc[mt][nt][q] = 0.f;

        if (t > 0) {
            const float* Abase = g_hbuf + (size_t)(t - 1) * BH;
            RLOADA(0, 0);
            RLOADB(0, 0);

            for (int kb = 0; kb < 32; kb++) {
                const int st = kb & 1;
                __syncthreads();
                if (kb < 31) { RLOADA(kb + 1, st ^ 1); RLOADB(kb + 1, st ^ 1); }

#pragma unroll
                for (int kt = 0; kt < 4; kt++) {
                    uint32_t ah[2][4], al[2][4];
#pragma unroll
                    for (int mt = 0; mt < 2; mt++) {
                        const int r = warp_m + mt * 16 + gr;
                        ah[mt][0] = sm->Ah[st][r][kt * 8 + cq];
                        ah[mt][1] = sm->Ah[st][r + 8][kt * 8 + cq];
                        ah[mt][2] = sm->Ah[st][r][kt * 8 + cq + 4];
                        ah[mt][3] = sm->Ah[st][r + 8][kt * 8 + cq + 4];
                        al[mt][0] = sm->Al[st][r][kt * 8 + cq];
                        al[mt][1] = sm->Al[st][r + 8][kt * 8 + cq];
                        al[mt][2] = sm->Al[st][r][kt * 8 + cq + 4];
                        al[mt][3] = sm->Al[st][r + 8][kt * 8 + cq + 4];
                    }
#pragma unroll
                    for (int nt = 0; nt < 2; nt++) {
                        const int cn = warp_n + nt * 8 + gr;
                        uint32_t bh0 = sm->Bh[st][cn][kt * 8 + cq];
                        uint32_t bh1 = sm->Bh[st][cn][kt * 8 + cq + 4];
                        uint32_t bl0 = sm->Bl[st][cn][kt * 8 + cq];
                        uint32_t bl1 = sm->Bl[st][cn][kt * 8 + cq + 4];
                        mma_tf32(acc[0][nt], al[0], bh0, bh1);
                        mma_tf32(acc[0][nt], ah[0], bl0, bl1);
                        mma_tf32(acc[0][nt], ah[0], bh0, bh1);
                        mma_tf32(acc[1][nt], al[1], bh0, bh1);
                        mma_tf32(acc[1][nt], ah[1], bl0, bl1);
                        mma_tf32(acc[1][nt], ah[1], bh0, bh1);
                    }
                }
            }

            // store gate sums to Gbuf
            __syncthreads();
#pragma unroll
            for (int mt = 0; mt < 2; mt++) {
#pragma unroll
                for (int nt = 0; nt < 2; nt++) {
                    const int r0  = warp_m + mt * 16 + gr;
                    const int col = warp_n + nt * 8 + 2 * cq;
                    sm->Gbuf[r0][col]         = acc[mt][nt][0];
                    sm->Gbuf[r0][col + 1]     = acc[mt][nt][1];
                    sm->Gbuf[r0 + 8][col]     = acc[mt][nt][2];
                    sm->Gbuf[r0 + 8][col + 1] = acc[mt][nt][3];
                }
            }
            __syncthreads();
        }

        // ---- pointwise (CTA-local, state in registers) ----
        {
            const float* preb = g_pre + (size_t)t * 4 * BH;
            float* hout = g_hbuf + (size_t)t * BH + (size_t)pb * HDIM + j0;
#pragma unroll
            for (int e = 0; e < 4; e++) {
                const int jl = pj + e;
                float fl, il, cl, ol;
                fl = __ldg(preb + (size_t)0 * BH + (size_t)pb * HDIM + j0 + jl);
                il = __ldg(preb + (size_t)1 * BH + (size_t)pb * HDIM + j0 + jl);
                cl = __ldg(preb + (size_t)2 * BH + (size_t)pb * HDIM + j0 + jl);
                ol = __ldg(preb + (size_t)3 * BH + (size_t)pb * HDIM + j0 + jl);
                if (t > 0) {
                    fl += sm->Gbuf[pb][0 * 8 + jl];
                    il += sm->Gbuf[pb][1 * 8 + jl];
                    cl += sm->Gbuf[pb][2 * 8 + jl];
                    ol += sm->Gbuf[pb][3 * 8 + jl];
                }
                float mn = fmaxf(fl + mS[e], il);
                float it = __expf(il - mn);
                float ft = __expf(fl + mS[e] - mn);
                float ch = tanhf(cl);
                float ot = 1.f / (1.f + __expf(-ol));

                float cn = ft * cS[e] + it * ch;
                float nn = ft * nS[e] + it;
                float hn = ot * (cn / (nn + 1e-8f));

                cS[e] = cn; nS[e] = nn; mS[e] = mn;
                hout[jl] = hn;
            }
        }

        grid_barrier();   // h_t visible before any CTA reads it at t+1
    }

#undef RLOADA
#undef RLOADB

    // final state
#pragma unroll
    for (int e = 0; e < 4; e++) {
        const int idx = pb * HDIM + j0 + pj + e;
        g_c[idx] = cS[e];
        g_n[idx] = nS[e];
        g_m[idx] = mS[e];
    }
}

// ---------------- tail: final h, c, n, m -----------------------------------
__global__ __launch_bounds__(256) void k_tail(float* __restrict__ out) {
    int i = blockIdx.x * blockDim.x + threadIdx.x;
    int which = i / BH;
    int r = i - which * BH;
    float v;
    if (which == 0)      v = g_hbuf[(size_t)(SEQ - 1) * BH + r];
    else if (which == 1) v = g_c[r];
    else if (which == 2) v = g_n[r];
    else                 v = g_m[r];
    out[(size_t)M1 * ODIM + i] = v;
}

// ---------------- launch ----------------------------------------------------
extern "C" void kernel_launch(void* const* d_in, const int* in_sizes, int n_in,
                              void* d_out, int out_size) {
    const float* x    = (const float*)d_in[0];
    const float* Wf   = (const float*)d_in[1];
    const float* bf   = (const float*)d_in[2];
    const float* Wi   = (const float*)d_in[3];
    const float* bi   = (const float*)d_in[4];
    const float* Wc   = (const float*)d_in[5];
    const float* bc   = (const float*)d_in[6];
    const float* Wo   = (const float*)d_in[7];
    const float* bo   = (const float*)d_in[8];
    const float* Wout = (const float*)d_in[9];
    const float* bout = (const float*)d_in[10];
    float* out = (float*)d_out;

    static int attr_done = 0;
    if (!attr_done) {
        cudaFuncSetAttribute(k_mma<0>, cudaFuncAttributeMaxDynamicSharedMemorySize, MSMEM_BYTES);
        cudaFuncSetAttribute(k_mma<1>, cudaFuncAttributeMaxDynamicSharedMemorySize, MSMEM_BYTES);
        cudaFuncSetAttribute(k_recur2, cudaFuncAttributeMaxDynamicSharedMemorySize, R2SMEM_BYTES);
        attr_done = 1;
    }

    // prep: split recurrent weights into tf32 hi/lo (blocked layout)
    k_split<<<dim3(4096, 4), 256>>>(Wf, Wi, Wc, Wo);

    // phase 1 (3xTF32 mma.sync): pre[t][g][b][:] = x @ Wg[:I] + bg
    k_mma<0><<<dim3(8, 512, 4), 256, MSMEM_BYTES>>>(
        x, Wf, Wi, Wc, Wo, bf, bi, bc, bo, nullptr);

    // recurrence (3xTF32 mma.sync, persistent, 1 CTA/SM)
    k_recur2<<<REC_BLOCKS, 256, R2SMEM_BYTES>>>();

    // output projection (3xTF32 mma.sync): out = hbuf @ Wout + bout
    k_mma<1><<<dim3(8, 512, 1), 256, MSMEM_BYTES>>>(
        nullptr, Wout, Wout, Wout, Wout, bout, bout, bout, bout, out);

    // final h, c, n, m
    k_tail<<<(4 * BH) / 256, 256>>>(out);
}